// round 1
// baseline (speedup 1.0000x reference)
#include <cuda_runtime.h>
#include <math.h>

#define SEQ    2048
#define TOKENS 4096
#define DIM    512
#define HEADS  8
#define HDIM   64
#define RANK   64
#define LAYERS 6
#define VOCAB  32000
#define FFD    2048
#define KTOP   409

// ---------------- scratch (static device globals: no allocs allowed) ----------------
__device__ float g_x[TOKENS * DIM];
__device__ float g_qkv[TOKENS * 3 * DIM];
__device__ float g_scores[(size_t)2 * HEADS * SEQ * SEQ];   // 268 MB
__device__ float g_dense[TOKENS * DIM];
__device__ float g_aproj[TOKENS * DIM];
__device__ float g_Qs[TOKENS * RANK];
__device__ float g_Ks[TOKENS * RANK];
__device__ float g_Vs[TOKENS * DIM];
__device__ float g_sparse[TOKENS * DIM];
__device__ float g_ffh[TOKENS * FFD];
__device__ float g_fft[TOKENS * DIM];

// ---------------- generic tiled GEMM: C = alpha * A @ op(B) + bias ----------------
// Tile 128(M) x 64(N) x 16(K), 256 threads, 8x4 micro-tile per thread.
// BNT=1: B is [N,K] row-major (C = A @ B^T).  BNT=0: B is [K,N] row-major (C = A @ B).
// Batched via blockIdx.z: z -> (zo = z/zdiv, zi = z%zdiv), pointer offsets per operand.
// Requires: M % 128 == 0, N % 64 == 0, K % 16 == 0, lda/ldb/ldc % 4 == 0,
//           all base offsets 16B aligned. (All uses satisfy this.)
template <int BNT>
__global__ void __launch_bounds__(256) gemm_k(
    const float* __restrict__ A, const float* __restrict__ B,
    const float* __restrict__ bias, float* __restrict__ C,
    int K, int lda, int ldb, int ldc,
    long sAo, long sAi, long sBo, long sBi, long sCo, long sCi,
    int zdiv, float alpha, int relu)
{
    __shared__ float As[16][132];
    __shared__ float Bs[16][68];

    int z = blockIdx.z;
    int zo = z / zdiv, zi = z - zo * zdiv;
    A += (long)zo * sAo + (long)zi * sAi;
    B += (long)zo * sBo + (long)zi * sBi;
    C += (long)zo * sCo + (long)zi * sCi;

    const int tid = threadIdx.x;
    const int m0 = blockIdx.y * 128;
    const int n0 = blockIdx.x * 64;
    const int lr  = tid >> 2;          // 0..63
    const int lk  = (tid & 3) << 2;    // 0,4,8,12
    const int lbk = tid >> 4;          // 0..15  (NN B-load)
    const int lbn = (tid & 15) << 2;   // 0..60
    const int tx = tid & 15, ty = tid >> 4;

    const float* Ap0 = A + (long)(m0 + lr) * lda + lk;
    const float* Ap1 = Ap0 + (long)64 * lda;
    const float* Bp  = BNT ? (B + (long)(n0 + lr) * ldb + lk)
                           : (B + (long)lbk * ldb + n0 + lbn);

    float acc[8][4];
#pragma unroll
    for (int i = 0; i < 8; i++)
#pragma unroll
        for (int j = 0; j < 4; j++) acc[i][j] = 0.f;

    for (int k0 = 0; k0 < K; k0 += 16) {
        float4 a0 = *(const float4*)(Ap0 + k0);
        float4 a1 = *(const float4*)(Ap1 + k0);
        float4 b0 = BNT ? *(const float4*)(Bp + k0)
                        : *(const float4*)(Bp + (long)k0 * ldb);
        __syncthreads();
        As[lk + 0][lr] = a0.x; As[lk + 1][lr] = a0.y;
        As[lk + 2][lr] = a0.z; As[lk + 3][lr] = a0.w;
        As[lk + 0][lr + 64] = a1.x; As[lk + 1][lr + 64] = a1.y;
        As[lk + 2][lr + 64] = a1.z; As[lk + 3][lr + 64] = a1.w;
        if (BNT) {
            Bs[lk + 0][lr] = b0.x; Bs[lk + 1][lr] = b0.y;
            Bs[lk + 2][lr] = b0.z; Bs[lk + 3][lr] = b0.w;
        } else {
            *(float4*)&Bs[lbk][lbn] = b0;
        }
        __syncthreads();
#pragma unroll
        for (int kk = 0; kk < 16; kk++) {
            float4 a4 = *(const float4*)&As[kk][ty * 8];
            float4 a5 = *(const float4*)&As[kk][ty * 8 + 4];
            float4 b4 = *(const float4*)&Bs[kk][tx * 4];
            float av[8] = {a4.x, a4.y, a4.z, a4.w, a5.x, a5.y, a5.z, a5.w};
            float bv[4] = {b4.x, b4.y, b4.z, b4.w};
#pragma unroll
            for (int i = 0; i < 8; i++)
#pragma unroll
                for (int j = 0; j < 4; j++)
                    acc[i][j] = fmaf(av[i], bv[j], acc[i][j]);
        }
    }

    float bj[4];
#pragma unroll
    for (int j = 0; j < 4; j++) bj[j] = bias ? bias[n0 + tx * 4 + j] : 0.f;
#pragma unroll
    for (int i = 0; i < 8; i++) {
        float4 o;
        o.x = acc[i][0] * alpha + bj[0];
        o.y = acc[i][1] * alpha + bj[1];
        o.z = acc[i][2] * alpha + bj[2];
        o.w = acc[i][3] * alpha + bj[3];
        if (relu) {
            o.x = fmaxf(o.x, 0.f); o.y = fmaxf(o.y, 0.f);
            o.z = fmaxf(o.z, 0.f); o.w = fmaxf(o.w, 0.f);
        }
        *(float4*)(C + (long)(m0 + ty * 8 + i) * ldc + n0 + tx * 4) = o;
    }
}

// ---------------- embedding ----------------
__global__ void embed_k(const int* __restrict__ src, const float* __restrict__ emb,
                        const float* __restrict__ pe, float* __restrict__ x)
{
    int t = blockIdx.x;
    int tid = threadIdx.x;
    int s = t & (SEQ - 1);
    int tok = src[t];
    int d = tid * 2;
    float2 e = *(const float2*)(emb + (long)tok * DIM + d);
    float2 p = *(const float2*)(pe + (long)s * DIM + d);
    float2 o;
    o.x = e.x * 22.627416998f + p.x;   // sqrt(512)
    o.y = e.y * 22.627416998f + p.y;
    *(float2*)(x + (long)t * DIM + d) = o;
}

// ---------------- row softmax over SEQ=2048 (in-place) ----------------
__global__ void softmax_rows(float* __restrict__ S)
{
    __shared__ float red[256];
    long row = blockIdx.x;
    float* p = S + row * (long)SEQ;
    int tid = threadIdx.x;
    float4 v0 = *(const float4*)(p + 4 * tid);
    float4 v1 = *(const float4*)(p + 4 * tid + 1024);
    float m = fmaxf(fmaxf(fmaxf(v0.x, v0.y), fmaxf(v0.z, v0.w)),
                    fmaxf(fmaxf(v1.x, v1.y), fmaxf(v1.z, v1.w)));
    red[tid] = m; __syncthreads();
    for (int s = 128; s > 0; s >>= 1) { if (tid < s) red[tid] = fmaxf(red[tid], red[tid + s]); __syncthreads(); }
    float M = red[0]; __syncthreads();
    v0.x = __expf(v0.x - M); v0.y = __expf(v0.y - M); v0.z = __expf(v0.z - M); v0.w = __expf(v0.w - M);
    v1.x = __expf(v1.x - M); v1.y = __expf(v1.y - M); v1.z = __expf(v1.z - M); v1.w = __expf(v1.w - M);
    float sum = v0.x + v0.y + v0.z + v0.w + v1.x + v1.y + v1.z + v1.w;
    red[tid] = sum; __syncthreads();
    for (int s = 128; s > 0; s >>= 1) { if (tid < s) red[tid] += red[tid + s]; __syncthreads(); }
    float inv = 1.f / red[0];
    v0.x *= inv; v0.y *= inv; v0.z *= inv; v0.w *= inv;
    v1.x *= inv; v1.y *= inv; v1.z *= inv; v1.w *= inv;
    *(float4*)(p + 4 * tid) = v0;
    *(float4*)(p + 4 * tid + 1024) = v1;
}

// ---------------- sparse low-rank attention (exact top-409 via radix select) ----------------
__device__ __forceinline__ unsigned f2k(float f)
{
    unsigned u = __float_as_uint(f);
    return (u & 0x80000000u) ? ~u : (u | 0x80000000u);   // order-preserving key
}

__global__ void __launch_bounds__(256) sparse_attn(
    const float* __restrict__ Qs, const float* __restrict__ Ks,
    const float* __restrict__ Vs, float* __restrict__ out)
{
    __shared__ float qv[RANK];
    __shared__ float logit[SEQ];
    __shared__ unsigned hist[256];
    __shared__ unsigned suf[256];
    __shared__ float red[256];
    __shared__ int sbase[256];
    __shared__ unsigned sh_prefix;
    __shared__ int sh_remaining;
    __shared__ int kidx[SEQ];
    __shared__ float kw[SEQ];

    int t = blockIdx.x, tid = threadIdx.x;
    int bb = t >> 11;
    const float* ksb = Ks + (long)bb * SEQ * RANK;
    const float* vsb = Vs + (long)bb * SEQ * DIM;

    if (tid < RANK / 4)
        ((float4*)qv)[tid] = ((const float4*)(Qs + (long)t * RANK))[tid];
    __syncthreads();

    // logits = Qs[t] . Ks[k] / sqrt(R)
    for (int k = tid; k < SEQ; k += 256) {
        const float4* kr = (const float4*)(ksb + (long)k * RANK);
        float acc = 0.f;
#pragma unroll
        for (int r = 0; r < RANK / 4; r++) {
            float4 kvv = kr[r]; float4 q4 = ((const float4*)qv)[r];
            acc += kvv.x * q4.x + kvv.y * q4.y + kvv.z * q4.z + kvv.w * q4.w;
        }
        logit[k] = acc * 0.125f;
    }
    __syncthreads();

    // row max
    float lm = -3.4e38f;
    for (int k = tid; k < SEQ; k += 256) lm = fmaxf(lm, logit[k]);
    red[tid] = lm; __syncthreads();
    for (int s = 128; s > 0; s >>= 1) { if (tid < s) red[tid] = fmaxf(red[tid], red[tid + s]); __syncthreads(); }
    float Lmax = red[0]; __syncthreads();

    // full partition function (for the reference's +1e-9 term)
    float zacc = 0.f;
    for (int k = tid; k < SEQ; k += 256) zacc += __expf(logit[k] - Lmax);
    red[tid] = zacc; __syncthreads();
    for (int s = 128; s > 0; s >>= 1) { if (tid < s) red[tid] += red[tid + s]; __syncthreads(); }
    float Z = red[0]; __syncthreads();

    // exact 409th-largest via 4x8-bit MSB radix select
    unsigned prefix = 0; int remaining = KTOP;
    for (int shift = 24; shift >= 0; shift -= 8) {
        hist[tid] = 0; __syncthreads();
        unsigned upmask = (shift == 24) ? 0u : (0xFFFFFFFFu << (shift + 8));
        for (int k = tid; k < SEQ; k += 256) {
            unsigned key = f2k(logit[k]);
            if ((key & upmask) == prefix)
                atomicAdd(&hist[(key >> shift) & 255], 1u);
        }
        __syncthreads();
        // inclusive suffix sum over 256 bins
        suf[tid] = hist[tid]; __syncthreads();
        for (int off = 1; off < 256; off <<= 1) {
            unsigned add = (tid + off < 256) ? suf[tid + off] : 0u;
            __syncthreads();
            suf[tid] += add;
            __syncthreads();
        }
        unsigned shere = suf[tid];
        unsigned snext = (tid < 255) ? suf[tid + 1] : 0u;
        if (shere >= (unsigned)remaining && snext < (unsigned)remaining) {
            sh_prefix = prefix | ((unsigned)tid << shift);
            sh_remaining = remaining - (int)snext;
        }
        __syncthreads();
        prefix = sh_prefix; remaining = sh_remaining;
        __syncthreads();
    }
    unsigned thr = prefix;

    // per-thread weights of kept entries (k = tid + 256j, deterministic order)
    float w8[8]; int myc = 0;
#pragma unroll
    for (int j = 0; j < 8; j++) {
        int k = tid + 256 * j;
        unsigned key = f2k(logit[k]);
        float w = (key >= thr) ? __expf(logit[k] - Lmax) : -1.f;
        w8[j] = w;
        if (w >= 0.f) myc++;
    }
    // deterministic compaction: inclusive prefix scan of counts
    sbase[tid] = myc; __syncthreads();
    for (int off = 1; off < 256; off <<= 1) {
        int add = (tid >= off) ? sbase[tid - off] : 0;
        __syncthreads();
        sbase[tid] += add;
        __syncthreads();
    }
    int p = sbase[tid] - myc;
    int ntot = sbase[255];
    float dsum = 0.f;
#pragma unroll
    for (int j = 0; j < 8; j++) {
        if (w8[j] >= 0.f) {
            kidx[p] = tid + 256 * j;
            kw[p] = w8[j];
            dsum += w8[j];
            p++;
        }
    }
    red[tid] = dsum; __syncthreads();
    for (int s = 128; s > 0; s >>= 1) { if (tid < s) red[tid] += red[tid + s]; __syncthreads(); }
    float inv = 1.f / (red[0] + 1e-9f * Z);
    __syncthreads();

    // sparse = sum_k w_k * Vs[k,:]
    int d = tid << 1;
    float a0 = 0.f, a1 = 0.f;
#pragma unroll 4
    for (int i = 0; i < ntot; i++) {
        int k = kidx[i]; float w = kw[i];
        float2 v = *(const float2*)(vsb + (long)k * DIM + d);
        a0 += w * v.x; a1 += w * v.y;
    }
    float2 o; o.x = a0 * inv; o.y = a1 * inv;
    *(float2*)(out + (long)t * DIM + d) = o;
}

// ---------------- gated fusion + LayerNorm1 (overwrites x) ----------------
__global__ void fuse_ln1_k(float* __restrict__ x, const float* __restrict__ dn,
                           const float* __restrict__ sp, const float* __restrict__ lam,
                           int layer, const float* __restrict__ gam, const float* __restrict__ bet)
{
    __shared__ float red[256];
    int row = blockIdx.x, tid = threadIdx.x;
    long off = (long)row * DIM + 2 * tid;
    float g = 1.f / (1.f + expf(-lam[layer]));
    float2 xv = *(const float2*)(x + off);
    float2 dv = *(const float2*)(dn + off);
    float2 sv = *(const float2*)(sp + off);
    float y0 = xv.x + g * dv.x + (1.f - g) * sv.x;
    float y1 = xv.y + g * dv.y + (1.f - g) * sv.y;
    red[tid] = y0 + y1; __syncthreads();
    for (int s = 128; s > 0; s >>= 1) { if (tid < s) red[tid] += red[tid + s]; __syncthreads(); }
    float mean = red[0] * (1.f / DIM); __syncthreads();
    float d0 = y0 - mean, d1 = y1 - mean;
    red[tid] = d0 * d0 + d1 * d1; __syncthreads();
    for (int s = 128; s > 0; s >>= 1) { if (tid < s) red[tid] += red[tid + s]; __syncthreads(); }
    float inv = 1.f / sqrtf(red[0] * (1.f / DIM) + 1e-5f);
    int dc = 2 * tid;
    float2 gm = *(const float2*)(gam + dc);
    float2 bt = *(const float2*)(bet + dc);
    float2 o; o.x = d0 * inv * gm.x + bt.x; o.y = d1 * inv * gm.y + bt.y;
    *(float2*)(x + off) = o;
}

// ---------------- residual + LayerNorm2 (overwrites x) ----------------
__global__ void add_ln2_k(float* __restrict__ x, const float* __restrict__ f,
                          const float* __restrict__ gam, const float* __restrict__ bet)
{
    __shared__ float red[256];
    int row = blockIdx.x, tid = threadIdx.x;
    long off = (long)row * DIM + 2 * tid;
    float2 xv = *(const float2*)(x + off);
    float2 fv = *(const float2*)(f + off);
    float y0 = xv.x + fv.x;
    float y1 = xv.y + fv.y;
    red[tid] = y0 + y1; __syncthreads();
    for (int s = 128; s > 0; s >>= 1) { if (tid < s) red[tid] += red[tid + s]; __syncthreads(); }
    float mean = red[0] * (1.f / DIM); __syncthreads();
    float d0 = y0 - mean, d1 = y1 - mean;
    red[tid] = d0 * d0 + d1 * d1; __syncthreads();
    for (int s = 128; s > 0; s >>= 1) { if (tid < s) red[tid] += red[tid + s]; __syncthreads(); }
    float inv = 1.f / sqrtf(red[0] * (1.f / DIM) + 1e-5f);
    int dc = 2 * tid;
    float2 gm = *(const float2*)(gam + dc);
    float2 bt = *(const float2*)(bet + dc);
    float2 o; o.x = d0 * inv * gm.x + bt.x; o.y = d1 * inv * gm.y + bt.y;
    *(float2*)(x + off) = o;
}

// ---------------- host-side launch helpers ----------------
static inline void gemm_nt(const float* A, const float* B, const float* bias, float* C,
                           int M, int N, int K, int lda, int ldb, int ldc,
                           int Z = 1, long sAo = 0, long sAi = 0, long sBo = 0, long sBi = 0,
                           long sCo = 0, long sCi = 0, int zdiv = 1,
                           float alpha = 1.f, int relu = 0)
{
    dim3 g(N / 64, M / 128, Z);
    gemm_k<1><<<g, 256>>>(A, B, bias, C, K, lda, ldb, ldc,
                          sAo, sAi, sBo, sBi, sCo, sCi, zdiv, alpha, relu);
}

static inline void gemm_nn(const float* A, const float* B, const float* bias, float* C,
                           int M, int N, int K, int lda, int ldb, int ldc,
                           int Z = 1, long sAo = 0, long sAi = 0, long sBo = 0, long sBi = 0,
                           long sCo = 0, long sCi = 0, int zdiv = 1,
                           float alpha = 1.f, int relu = 0)
{
    dim3 g(N / 64, M / 128, Z);
    gemm_k<0><<<g, 256>>>(A, B, bias, C, K, lda, ldb, ldc,
                          sAo, sAi, sBo, sBi, sCo, sCi, zdiv, alpha, relu);
}

extern "C" void kernel_launch(void* const* d_in, const int* in_sizes, int n_in,
                              void* d_out, int out_size)
{
    const int*   SRC   = (const int*)  d_in[0];
    const float* EMB   = (const float*)d_in[1];
    const float* PE    = (const float*)d_in[2];
    const float* IN_W  = (const float*)d_in[3];
    const float* IN_B  = (const float*)d_in[4];
    const float* OUT_W = (const float*)d_in[5];
    const float* OUT_B = (const float*)d_in[6];
    const float* QP_W  = (const float*)d_in[7];
    const float* QP_B  = (const float*)d_in[8];
    const float* KP_W  = (const float*)d_in[9];
    const float* KP_B  = (const float*)d_in[10];
    const float* VP_W  = (const float*)d_in[11];
    const float* VP_B  = (const float*)d_in[12];
    const float* LAM   = (const float*)d_in[13];
    const float* FF1_W = (const float*)d_in[14];
    const float* FF1_B = (const float*)d_in[15];
    const float* FF2_W = (const float*)d_in[16];
    const float* FF2_B = (const float*)d_in[17];
    const float* LN1S  = (const float*)d_in[18];
    const float* LN1B  = (const float*)d_in[19];
    const float* LN2S  = (const float*)d_in[20];
    const float* LN2B  = (const float*)d_in[21];
    const float* FIN_W = (const float*)d_in[22];
    const float* FIN_B = (const float*)d_in[23];
    float* OUT = (float*)d_out;

    float *x, *qkv, *scores, *dense, *aproj, *qs, *ks, *vs, *sp, *ffh, *fft;
    cudaGetSymbolAddress((void**)&x,      g_x);
    cudaGetSymbolAddress((void**)&qkv,    g_qkv);
    cudaGetSymbolAddress((void**)&scores, g_scores);
    cudaGetSymbolAddress((void**)&dense,  g_dense);
    cudaGetSymbolAddress((void**)&aproj,  g_aproj);
    cudaGetSymbolAddress((void**)&qs,     g_Qs);
    cudaGetSymbolAddress((void**)&ks,     g_Ks);
    cudaGetSymbolAddress((void**)&vs,     g_Vs);
    cudaGetSymbolAddress((void**)&sp,     g_sparse);
    cudaGetSymbolAddress((void**)&ffh,    g_ffh);
    cudaGetSymbolAddress((void**)&fft,    g_fft);

    embed_k<<<TOKENS, 256>>>(SRC, EMB, PE, x);

    for (int l = 0; l < LAYERS; l++) {
        const float* in_w  = IN_W  + (long)l * 3 * DIM * DIM;
        const float* in_b  = IN_B  + (long)l * 3 * DIM;
        const float* out_w = OUT_W + (long)l * DIM * DIM;
        const float* out_b = OUT_B + (long)l * DIM;
        const float* qp_w  = QP_W  + (long)l * RANK * DIM;
        const float* qp_b  = QP_B  + (long)l * RANK;
        const float* kp_w  = KP_W  + (long)l * RANK * DIM;
        const float* kp_b  = KP_B  + (long)l * RANK;
        const float* vp_w  = VP_W  + (long)l * DIM * DIM;
        const float* vp_b  = VP_B  + (long)l * DIM;
        const float* f1w   = FF1_W + (long)l * FFD * DIM;
        const float* f1b   = FF1_B + (long)l * FFD;
        const float* f2w   = FF2_W + (long)l * DIM * FFD;
        const float* f2b   = FF2_B + (long)l * DIM;

        // qkv = x @ in_w^T + in_b
        gemm_nt(x, in_w, in_b, qkv, TOKENS, 3 * DIM, DIM, DIM, DIM, 3 * DIM);

        // dense attention scores per (b,h): S = Q @ K^T / 8
        gemm_nt(qkv, qkv + DIM, nullptr, scores,
                SEQ, SEQ, HDIM, 3 * DIM, 3 * DIM, SEQ,
                /*Z=*/16,
                (long)SEQ * 3 * DIM, (long)HDIM,       // A (Q) strides per b, h
                (long)SEQ * 3 * DIM, (long)HDIM,       // B (K) strides per b, h
                (long)HEADS * SEQ * SEQ, (long)SEQ * SEQ,
                HEADS, 0.125f, 0);

        softmax_rows<<<2 * HEADS * SEQ, 256>>>(scores);

        // dense = P @ V  (per (b,h), written into head slots of [T,512])
        gemm_nn(scores, qkv + 2 * DIM, nullptr, dense,
                SEQ, HDIM, SEQ, SEQ, 3 * DIM, DIM,
                /*Z=*/16,
                (long)HEADS * SEQ * SEQ, (long)SEQ * SEQ,
                (long)SEQ * 3 * DIM, (long)HDIM,
                (long)SEQ * DIM, (long)HDIM,
                HEADS, 1.f, 0);

        // dense projection
        gemm_nt(dense, out_w, out_b, aproj, TOKENS, DIM, DIM, DIM, DIM, DIM);

        // low-rank projections
        gemm_nt(x, qp_w, qp_b, qs, TOKENS, RANK, DIM, DIM, DIM, RANK);
        gemm_nt(x, kp_w, kp_b, ks, TOKENS, RANK, DIM, DIM, DIM, RANK);
        gemm_nt(x, vp_w, vp_b, vs, TOKENS, DIM, DIM, DIM, DIM, DIM);

        // exact top-409 sparse path
        sparse_attn<<<TOKENS, 256>>>(qs, ks, vs, sp);

        // gated fusion + LN1
        fuse_ln1_k<<<TOKENS, 256>>>(x, aproj, sp, LAM, l,
                                    LN1S + (long)l * DIM, LN1B + (long)l * DIM);

        // FFN
        gemm_nt(x, f1w, f1b, ffh, TOKENS, FFD, DIM, DIM, DIM, FFD,
                1, 0, 0, 0, 0, 0, 0, 1, 1.f, /*relu=*/1);
        gemm_nt(ffh, f2w, f2b, fft, TOKENS, DIM, FFD, FFD, FFD, DIM);

        // residual + LN2
        add_ln2_k<<<TOKENS, 256>>>(x, fft, LN2S + (long)l * DIM, LN2B + (long)l * DIM);
    }

    // final vocab projection directly into d_out
    gemm_nt(x, FIN_W, FIN_B, OUT, TOKENS, VOCAB, DIM, DIM, DIM, VOCAB);
}

// round 4
// speedup vs baseline: 1.5140x; 1.5140x over previous
#include <cuda_runtime.h>
#include <cuda_bf16.h>
#include <math.h>
#include <stdint.h>

#define SEQ    2048
#define TOKENS 4096
#define DIM    512
#define HEADS  8
#define HDIM   64
#define RANK   64
#define LAYERS 6
#define VOCAB  32000
#define FFD    2048
#define KTOP   409

typedef unsigned short u16;

// ---------------- fp32 scratch ----------------
__device__ float g_x[TOKENS * DIM];
__device__ float g_qkv[TOKENS * 3 * DIM];
__device__ float g_scores[(size_t)16 * SEQ * SEQ];
__device__ float g_dense[TOKENS * DIM];
__device__ float g_aproj[TOKENS * DIM];
__device__ float g_Qs[TOKENS * RANK];
__device__ float g_Ks[TOKENS * RANK];
__device__ float g_Vs[TOKENS * DIM];
__device__ float g_sparse[TOKENS * DIM];
__device__ float g_ffh[TOKENS * FFD];
__device__ float g_fft[TOKENS * DIM];

// ---------------- bf16 hi/lo planes (activations) ----------------
__device__ alignas(16) u16 g_xh[TOKENS * DIM],       g_xl[TOKENS * DIM];
__device__ alignas(16) u16 g_qkvh[TOKENS * 3 * DIM], g_qkvl[TOKENS * 3 * DIM];
__device__ alignas(16) u16 g_Ph[(size_t)16 * SEQ * SEQ], g_Pl[(size_t)16 * SEQ * SEQ];
__device__ alignas(16) u16 g_dh[TOKENS * DIM],       g_dl[TOKENS * DIM];
__device__ alignas(16) u16 g_fh[TOKENS * FFD],       g_fl[TOKENS * FFD];
__device__ alignas(16) u16 g_vth[16 * HDIM * SEQ],   g_vtl[16 * HDIM * SEQ];

// ---------------- bf16 hi/lo planes (weights) ----------------
__device__ alignas(16) u16 g_inwh[LAYERS * 3 * DIM * DIM], g_inwl[LAYERS * 3 * DIM * DIM];
__device__ alignas(16) u16 g_outwh[LAYERS * DIM * DIM],    g_outwl[LAYERS * DIM * DIM];
__device__ alignas(16) u16 g_qpwh[LAYERS * RANK * DIM],    g_qpwl[LAYERS * RANK * DIM];
__device__ alignas(16) u16 g_kpwh[LAYERS * RANK * DIM],    g_kpwl[LAYERS * RANK * DIM];
__device__ alignas(16) u16 g_vpwh[LAYERS * DIM * DIM],     g_vpwl[LAYERS * DIM * DIM];
__device__ alignas(16) u16 g_f1wh[LAYERS * FFD * DIM],     g_f1wl[LAYERS * FFD * DIM];
__device__ alignas(16) u16 g_f2wh[LAYERS * DIM * FFD],     g_f2wl[LAYERS * DIM * FFD];
__device__ alignas(16) u16 g_finwh[VOCAB * DIM],           g_finwl[VOCAB * DIM];

// ---------------- small device helpers ----------------
__device__ __forceinline__ void fsplit(float x, u16& h, u16& l)
{
    __nv_bfloat16 bh = __float2bfloat16_rn(x);
    float fh = __bfloat162float(bh);
    __nv_bfloat16 bl = __float2bfloat16_rn(x - fh);
    h = *reinterpret_cast<u16*>(&bh);
    l = *reinterpret_cast<u16*>(&bl);
}

__device__ __forceinline__ uint32_t smem_u32(const void* p)
{
    uint32_t a;
    asm("{ .reg .u64 t; cvta.to.shared.u64 t, %1; cvt.u32.u64 %0, t; }" : "=r"(a) : "l"(p));
    return a;
}

__device__ __forceinline__ void cpa16(uint32_t dst, const void* src)
{
    asm volatile("cp.async.cg.shared.global [%0], [%1], 16;" :: "r"(dst), "l"(src) : "memory");
}

__device__ __forceinline__ void ldsm4(uint32_t* r, uint32_t addr)
{
    asm volatile("ldmatrix.sync.aligned.m8n8.x4.shared.b16 {%0,%1,%2,%3}, [%4];"
                 : "=r"(r[0]), "=r"(r[1]), "=r"(r[2]), "=r"(r[3]) : "r"(addr));
}

__device__ __forceinline__ void mma16816(float* c, const uint32_t* a, uint32_t b0, uint32_t b1)
{
    asm volatile(
        "mma.sync.aligned.m16n8k16.row.col.f32.bf16.bf16.f32 "
        "{%0,%1,%2,%3}, {%4,%5,%6,%7}, {%8,%9}, {%0,%1,%2,%3};"
        : "+f"(c[0]), "+f"(c[1]), "+f"(c[2]), "+f"(c[3])
        : "r"(a[0]), "r"(a[1]), "r"(a[2]), "r"(a[3]), "r"(b0), "r"(b1));
}

// ---------------- HMMA bf16x3 GEMM: C = alpha * (A @ B^T) + bias ----------------
// A planes [M,K] bf16 hi/lo row-major; B planes [N,K] bf16 hi/lo row-major.
// CTA tile 128 x TN, K chunk 32, cp.async double buffer, 80B-padded smem rows.
template <int TN>
__global__ void __launch_bounds__(256)
mm_gemm(const u16* __restrict__ Ah, const u16* __restrict__ Al,
        const u16* __restrict__ Bh, const u16* __restrict__ Bl,
        const float* __restrict__ bias, float* __restrict__ C,
        u16* __restrict__ Ch, u16* __restrict__ Cl,
        int K, int lda, int ldb, int ldc,
        long sAo, long sAi, long sBo, long sBi, long sCo, long sCi,
        int zdiv, float alpha, int relu)
{
    constexpr int MI  = (TN == 128) ? 4 : 2;   // 16-row A frags per warp
    constexpr int APB = 128 * 80;              // A plane bytes per stage
    constexpr int BPB = TN * 80;
    constexpr int STAGE = 2 * APB + 2 * BPB;

    extern __shared__ char smem[];
    const uint32_t su = smem_u32(smem);
    const int tid = threadIdx.x;
    const int wid = tid >> 5;
    const int lane = tid & 31;

    int z = blockIdx.z;
    int zo = z / zdiv, zi = z - zo * zdiv;
    long ao = (long)zo * sAo + (long)zi * sAi;
    long bo = (long)zo * sBo + (long)zi * sBi;
    long co = (long)zo * sCo + (long)zi * sCi;
    Ah += ao; Al += ao; Bh += bo; Bl += bo; C += co;
    if (Ch) { Ch += co; Cl += co; }
    const int m0 = blockIdx.y * 128;
    const int n0 = blockIdx.x * TN;

    const int wmBase = (TN == 128) ? (wid & 1) * 64 : (wid & 3) * 32;
    const int wnBase = (TN == 128) ? (wid >> 1) * 32 : (wid >> 2) * 32;

    float acc[MI][4][4];
#pragma unroll
    for (int mi = 0; mi < MI; mi++)
#pragma unroll
        for (int n8 = 0; n8 < 4; n8++)
#pragma unroll
            for (int q = 0; q < 4; q++) acc[mi][n8][q] = 0.f;

    const int nch = K >> 5;

    // ---- async loader for chunk i ----
    const int ar = tid >> 2, ac = tid & 3;     // 4 x 16B chunks per 80B row
    auto issue = [&](int i) {
        int s = i & 1;
        int k0 = i << 5;
        uint32_t st = su + s * STAGE;
#pragma unroll
        for (int j = 0; j < 2; j++) {
            int r = ar + 64 * j;
            long g = (long)(m0 + r) * lda + k0 + ac * 8;
            uint32_t d = st + r * 80 + ac * 16;
            cpa16(d, Ah + g);
            cpa16(d + APB, Al + g);
        }
#pragma unroll
        for (int j = 0; j < TN / 64; j++) {
            int r = ar + 64 * j;
            long g = (long)(n0 + r) * ldb + k0 + ac * 8;
            uint32_t d = st + 2 * APB + r * 80 + ac * 16;
            cpa16(d, Bh + g);
            cpa16(d + BPB, Bl + g);
        }
        asm volatile("cp.async.commit_group;" ::: "memory");
    };

    issue(0);
    const uint32_t lrow = lane & 15;
    const uint32_t lcol = (lane >> 4) * 16;    // byte offset of 8-col group

    for (int i = 0; i < nch; i++) {
        if (i + 1 < nch) {
            issue(i + 1);
            asm volatile("cp.async.wait_group 1;" ::: "memory");
        } else {
            asm volatile("cp.async.wait_group 0;" ::: "memory");
        }
        __syncthreads();

        int s = i & 1;
        uint32_t aH = su + s * STAGE;
        uint32_t aL = aH + APB;
        uint32_t bH = aH + 2 * APB;
        uint32_t bL = bH + BPB;

#pragma unroll
        for (int ks = 0; ks < 2; ks++) {
            uint32_t a[MI][4], bh[2][4], bl[2][4];
            uint32_t kb = ks * 32 + lcol;
#pragma unroll
            for (int mi = 0; mi < MI; mi++)
                ldsm4(a[mi], aH + (wmBase + mi * 16 + lrow) * 80 + kb);
#pragma unroll
            for (int ni = 0; ni < 2; ni++)
                ldsm4(bh[ni], bH + (wnBase + ni * 16 + lrow) * 80 + kb);
            // pass 1: Ah * Bh
#pragma unroll
            for (int mi = 0; mi < MI; mi++)
#pragma unroll
                for (int ni = 0; ni < 2; ni++) {
                    mma16816(acc[mi][2 * ni],     a[mi], bh[ni][0], bh[ni][2]);
                    mma16816(acc[mi][2 * ni + 1], a[mi], bh[ni][1], bh[ni][3]);
                }
            // pass 2: Ah * Bl
#pragma unroll
            for (int ni = 0; ni < 2; ni++)
                ldsm4(bl[ni], bL + (wnBase + ni * 16 + lrow) * 80 + kb);
#pragma unroll
            for (int mi = 0; mi < MI; mi++)
#pragma unroll
                for (int ni = 0; ni < 2; ni++) {
                    mma16816(acc[mi][2 * ni],     a[mi], bl[ni][0], bl[ni][2]);
                    mma16816(acc[mi][2 * ni + 1], a[mi], bl[ni][1], bl[ni][3]);
                }
            // pass 3: Al * Bh
#pragma unroll
            for (int mi = 0; mi < MI; mi++)
                ldsm4(a[mi], aL + (wmBase + mi * 16 + lrow) * 80 + kb);
#pragma unroll
            for (int mi = 0; mi < MI; mi++)
#pragma unroll
                for (int ni = 0; ni < 2; ni++) {
                    mma16816(acc[mi][2 * ni],     a[mi], bh[ni][0], bh[ni][2]);
                    mma16816(acc[mi][2 * ni + 1], a[mi], bh[ni][1], bh[ni][3]);
                }
        }
        __syncthreads();
    }

    // ---- epilogue ----
#pragma unroll
    for (int mi = 0; mi < MI; mi++) {
        int r0 = m0 + wmBase + mi * 16 + (lane >> 2);
#pragma unroll
        for (int n8 = 0; n8 < 4; n8++) {
            int c = n0 + wnBase + n8 * 8 + (lane & 3) * 2;
            float2 o0, o1;
            o0.x = acc[mi][n8][0] * alpha; o0.y = acc[mi][n8][1] * alpha;
            o1.x = acc[mi][n8][2] * alpha; o1.y = acc[mi][n8][3] * alpha;
            if (bias) {
                float b0 = bias[c], b1 = bias[c + 1];
                o0.x += b0; o0.y += b1; o1.x += b0; o1.y += b1;
            }
            if (relu) {
                o0.x = fmaxf(o0.x, 0.f); o0.y = fmaxf(o0.y, 0.f);
                o1.x = fmaxf(o1.x, 0.f); o1.y = fmaxf(o1.y, 0.f);
            }
            long off0 = (long)r0 * ldc + c;
            long off1 = off0 + (long)8 * ldc;
            *(float2*)(C + off0) = o0;
            *(float2*)(C + off1) = o1;
            if (Ch) {
                ushort2 hh, ll;
                fsplit(o0.x, hh.x, ll.x); fsplit(o0.y, hh.y, ll.y);
                *(ushort2*)(Ch + off0) = hh; *(ushort2*)(Cl + off0) = ll;
                fsplit(o1.x, hh.x, ll.x); fsplit(o1.y, hh.y, ll.y);
                *(ushort2*)(Ch + off1) = hh; *(ushort2*)(Cl + off1) = ll;
            }
        }
    }
}

// ---------------- converters ----------------
__global__ void cvt_k(const float4* __restrict__ s, ushort4* __restrict__ h,
                      ushort4* __restrict__ l, int n4)
{
    int i = blockIdx.x * 256 + threadIdx.x;
    if (i >= n4) return;
    float4 v = s[i];
    ushort4 hh, ll;
    fsplit(v.x, hh.x, ll.x); fsplit(v.y, hh.y, ll.y);
    fsplit(v.z, hh.z, ll.z); fsplit(v.w, hh.w, ll.w);
    h[i] = hh; l[i] = ll;
}

// V^T planes from qkv fp32: vt[z][d][s] = qkv[(b*2048+s)][1024 + h*64 + d]
__global__ void vt_k(const float* __restrict__ qkv, u16* __restrict__ vh, u16* __restrict__ vl)
{
    int s = blockIdx.x * 256 + threadIdx.x;
    int d = blockIdx.y;
    int z = blockIdx.z;
    int b = z >> 3, h = z & 7;
    float v = qkv[((long)(b * SEQ + s)) * (3 * DIM) + 2 * DIM + h * HDIM + d];
    long o = ((long)z * HDIM + d) * SEQ + s;
    fsplit(v, vh[o], vl[o]);
}

// ---------------- embedding (+ x planes) ----------------
__global__ void embed_k(const int* __restrict__ src, const float* __restrict__ emb,
                        const float* __restrict__ pe, float* __restrict__ x,
                        u16* __restrict__ xh, u16* __restrict__ xl)
{
    int t = blockIdx.x;
    int tid = threadIdx.x;
    int s = t & (SEQ - 1);
    int tok = src[t];
    int d = tid * 2;
    float2 e = *(const float2*)(emb + (long)tok * DIM + d);
    float2 p = *(const float2*)(pe + (long)s * DIM + d);
    float2 o;
    o.x = e.x * 22.627416998f + p.x;
    o.y = e.y * 22.627416998f + p.y;
    long off = (long)t * DIM + d;
    *(float2*)(x + off) = o;
    ushort2 hh, ll;
    fsplit(o.x, hh.x, ll.x); fsplit(o.y, hh.y, ll.y);
    *(ushort2*)(xh + off) = hh;
    *(ushort2*)(xl + off) = ll;
}

// ---------------- row softmax -> P hi/lo planes ----------------
__global__ void softmax_rows(const float* __restrict__ S, u16* __restrict__ Ph,
                             u16* __restrict__ Pl)
{
    __shared__ float red[256];
    long row = blockIdx.x;
    const float* p = S + row * (long)SEQ;
    int tid = threadIdx.x;
    float4 v0 = *(const float4*)(p + 4 * tid);
    float4 v1 = *(const float4*)(p + 4 * tid + 1024);
    float m = fmaxf(fmaxf(fmaxf(v0.x, v0.y), fmaxf(v0.z, v0.w)),
                    fmaxf(fmaxf(v1.x, v1.y), fmaxf(v1.z, v1.w)));
    red[tid] = m; __syncthreads();
    for (int s = 128; s > 0; s >>= 1) { if (tid < s) red[tid] = fmaxf(red[tid], red[tid + s]); __syncthreads(); }
    float M = red[0]; __syncthreads();
    v0.x = __expf(v0.x - M); v0.y = __expf(v0.y - M); v0.z = __expf(v0.z - M); v0.w = __expf(v0.w - M);
    v1.x = __expf(v1.x - M); v1.y = __expf(v1.y - M); v1.z = __expf(v1.z - M); v1.w = __expf(v1.w - M);
    float sum = v0.x + v0.y + v0.z + v0.w + v1.x + v1.y + v1.z + v1.w;
    red[tid] = sum; __syncthreads();
    for (int s = 128; s > 0; s >>= 1) { if (tid < s) red[tid] += red[tid + s]; __syncthreads(); }
    float inv = 1.f / red[0];
    v0.x *= inv; v0.y *= inv; v0.z *= inv; v0.w *= inv;
    v1.x *= inv; v1.y *= inv; v1.z *= inv; v1.w *= inv;
    long b0 = row * (long)SEQ + 4 * tid;
    ushort4 hh, ll;
    fsplit(v0.x, hh.x, ll.x); fsplit(v0.y, hh.y, ll.y);
    fsplit(v0.z, hh.z, ll.z); fsplit(v0.w, hh.w, ll.w);
    *(ushort4*)(Ph + b0) = hh; *(ushort4*)(Pl + b0) = ll;
    fsplit(v1.x, hh.x, ll.x); fsplit(v1.y, hh.y, ll.y);
    fsplit(v1.z, hh.z, ll.z); fsplit(v1.w, hh.w, ll.w);
    *(ushort4*)(Ph + b0 + 1024) = hh; *(ushort4*)(Pl + b0 + 1024) = ll;
}

// ---------------- sparse low-rank attention (exact top-409 via radix select) ----------------
__device__ __forceinline__ unsigned f2k(float f)
{
    unsigned u = __float_as_uint(f);
    return (u & 0x80000000u) ? ~u : (u | 0x80000000u);
}

__global__ void __launch_bounds__(256) sparse_attn(
    const float* __restrict__ Qs, const float* __restrict__ Ks,
    const float* __restrict__ Vs, float* __restrict__ out)
{
    __shared__ float qv[RANK];
    __shared__ float logit[SEQ];
    __shared__ unsigned hist[256];
    __shared__ unsigned suf[256];
    __shared__ float red[256];
    __shared__ int sbase[256];
    __shared__ unsigned sh_prefix;
    __shared__ int sh_remaining;
    __shared__ int kidx[SEQ];
    __shared__ float kw[SEQ];

    int t = blockIdx.x, tid = threadIdx.x;
    int bb = t >> 11;
    const float* ksb = Ks + (long)bb * SEQ * RANK;
    const float* vsb = Vs + (long)bb * SEQ * DIM;

    if (tid < RANK / 4)
        ((float4*)qv)[tid] = ((const float4*)(Qs + (long)t * RANK))[tid];
    __syncthreads();

    for (int k = tid; k < SEQ; k += 256) {
        const float4* kr = (const float4*)(ksb + (long)k * RANK);
        float acc = 0.f;
#pragma unroll
        for (int r = 0; r < RANK / 4; r++) {
            float4 kvv = kr[r]; float4 q4 = ((const float4*)qv)[r];
            acc += kvv.x * q4.x + kvv.y * q4.y + kvv.z * q4.z + kvv.w * q4.w;
        }
        logit[k] = acc * 0.125f;
    }
    __syncthreads();

    float lm = -3.4e38f;
    for (int k = tid; k < SEQ; k += 256) lm = fmaxf(lm, logit[k]);
    red[tid] = lm; __syncthreads();
    for (int s = 128; s > 0; s >>= 1) { if (tid < s) red[tid] = fmaxf(red[tid], red[tid + s]); __syncthreads(); }
    float Lmax = red[0]; __syncthreads();

    float zacc = 0.f;
    for (int k = tid; k < SEQ; k += 256) zacc += __expf(logit[k] - Lmax);
    red[tid] = zacc; __syncthreads();
    for (int s = 128; s > 0; s >>= 1) { if (tid < s) red[tid] += red[tid + s]; __syncthreads(); }
    float Z = red[0]; __syncthreads();

    unsigned prefix = 0; int remaining = KTOP;
    for (int shift = 24; shift >= 0; shift -= 8) {
        hist[tid] = 0; __syncthreads();
        unsigned upmask = (shift == 24) ? 0u : (0xFFFFFFFFu << (shift + 8));
        for (int k = tid; k < SEQ; k += 256) {
            unsigned key = f2k(logit[k]);
            if ((key & upmask) == prefix)
                atomicAdd(&hist[(key >> shift) & 255], 1u);
        }
        __syncthreads();
        suf[tid] = hist[tid]; __syncthreads();
        for (int off = 1; off < 256; off <<= 1) {
            unsigned add = (tid + off < 256) ? suf[tid + off] : 0u;
            __syncthreads();
            suf[tid] += add;
            __syncthreads();
        }
        unsigned shere = suf[tid];
        unsigned snext = (tid < 255) ? suf[tid + 1] : 0u;
        if (shere >= (unsigned)remaining && snext < (unsigned)remaining) {
            sh_prefix = prefix | ((unsigned)tid << shift);
            sh_remaining = remaining - (int)snext;
        }
        __syncthreads();
        prefix = sh_prefix; remaining = sh_remaining;
        __syncthreads();
    }
    unsigned thr = prefix;

    float w8[8]; int myc = 0;
#pragma unroll
    for (int j = 0; j < 8; j++) {
        int k = tid + 256 * j;
        unsigned key = f2k(logit[k]);
        float w = (key >= thr) ? __expf(logit[k] - Lmax) : -1.f;
        w8[j] = w;
        if (w >= 0.f) myc++;
    }
    sbase[tid] = myc; __syncthreads();
    for (int off = 1; off < 256; off <<= 1) {
        int add = (tid >= off) ? sbase[tid - off] : 0;
        __syncthreads();
        sbase[tid] += add;
        __syncthreads();
    }
    int p = sbase[tid] - myc;
    int ntot = sbase[255];
    float dsum = 0.f;
#pragma unroll
    for (int j = 0; j < 8; j++) {
        if (w8[j] >= 0.f) {
            kidx[p] = tid + 256 * j;
            kw[p] = w8[j];
            dsum += w8[j];
            p++;
        }
    }
    red[tid] = dsum; __syncthreads();
    for (int s = 128; s > 0; s >>= 1) { if (tid < s) red[tid] += red[tid + s]; __syncthreads(); }
    float inv = 1.f / (red[0] + 1e-9f * Z);
    __syncthreads();

    int d = tid << 1;
    float a0 = 0.f, a1 = 0.f;
#pragma unroll 4
    for (int i = 0; i < ntot; i++) {
        int k = kidx[i]; float w = kw[i];
        float2 v = *(const float2*)(vsb + (long)k * DIM + d);
        a0 += w * v.x; a1 += w * v.y;
    }
    float2 o; o.x = a0 * inv; o.y = a1 * inv;
    *(float2*)(out + (long)t * DIM + d) = o;
}

// ---------------- gated fusion + LN1 (overwrites x, emits x planes) ----------------
__global__ void fuse_ln1_k(float* __restrict__ x, const float* __restrict__ dn,
                           const float* __restrict__ sp, const float* __restrict__ lam,
                           int layer, const float* __restrict__ gam, const float* __restrict__ bet,
                           u16* __restrict__ xh, u16* __restrict__ xl)
{
    __shared__ float red[256];
    int row = blockIdx.x, tid = threadIdx.x;
    long off = (long)row * DIM + 2 * tid;
    float g = 1.f / (1.f + expf(-lam[layer]));
    float2 xv = *(const float2*)(x + off);
    float2 dv = *(const float2*)(dn + off);
    float2 sv = *(const float2*)(sp + off);
    float y0 = xv.x + g * dv.x + (1.f - g) * sv.x;
    float y1 = xv.y + g * dv.y + (1.f - g) * sv.y;
    red[tid] = y0 + y1; __syncthreads();
    for (int s = 128; s > 0; s >>= 1) { if (tid < s) red[tid] += red[tid + s]; __syncthreads(); }
    float mean = red[0] * (1.f / DIM); __syncthreads();
    float d0 = y0 - mean, d1 = y1 - mean;
    red[tid] = d0 * d0 + d1 * d1; __syncthreads();
    for (int s = 128; s > 0; s >>= 1) { if (tid < s) red[tid] += red[tid + s]; __syncthreads(); }
    float inv = 1.f / sqrtf(red[0] * (1.f / DIM) + 1e-5f);
    int dc = 2 * tid;
    float2 gm = *(const float2*)(gam + dc);
    float2 bt = *(const float2*)(bet + dc);
    float2 o; o.x = d0 * inv * gm.x + bt.x; o.y = d1 * inv * gm.y + bt.y;
    *(float2*)(x + off) = o;
    ushort2 hh, ll;
    fsplit(o.x, hh.x, ll.x); fsplit(o.y, hh.y, ll.y);
    *(ushort2*)(xh + off) = hh;
    *(ushort2*)(xl + off) = ll;
}

// ---------------- residual + LN2 (overwrites x, emits x planes) ----------------
__global__ void add_ln2_k(float* __restrict__ x, const float* __restrict__ f,
                          const float* __restrict__ gam, const float* __restrict__ bet,
                          u16* __restrict__ xh, u16* __restrict__ xl)
{
    __shared__ float red[256];
    int row = blockIdx.x, tid = threadIdx.x;
    long off = (long)row * DIM + 2 * tid;
    float2 xv = *(const float2*)(x + off);
    float2 fv = *(const float2*)(f + off);
    float y0 = xv.x + fv.x;
    float y1 = xv.y + fv.y;
    red[tid] = y0 + y1; __syncthreads();
    for (int s = 128; s > 0; s >>= 1) { if (tid < s) red[tid] += red[tid + s]; __syncthreads(); }
    float mean = red[0] * (1.f / DIM); __syncthreads();
    float d0 = y0 - mean, d1 = y1 - mean;
    red[tid] = d0 * d0 + d1 * d1; __syncthreads();
    for (int s = 128; s > 0; s >>= 1) { if (tid < s) red[tid] += red[tid + s]; __syncthreads(); }
    float inv = 1.f / sqrtf(red[0] * (1.f / DIM) + 1e-5f);
    int dc = 2 * tid;
    float2 gm = *(const float2*)(gam + dc);
    float2 bt = *(const float2*)(bet + dc);
    float2 o; o.x = d0 * inv * gm.x + bt.x; o.y = d1 * inv * gm.y + bt.y;
    *(float2*)(x + off) = o;
    ushort2 hh, ll;
    fsplit(o.x, hh.x, ll.x); fsplit(o.y, hh.y, ll.y);
    *(ushort2*)(xh + off) = hh;
    *(ushort2*)(xl + off) = ll;
}

// ---------------- host-side helpers ----------------
template <int TN>
static void launch_tc(const u16* Ah, const u16* Al, const u16* Bh, const u16* Bl,
                      const float* bias, float* C, u16* Ch, u16* Cl,
                      int M, int N, int K, int lda, int ldb, int ldc,
                      int Z = 1, long sAo = 0, long sAi = 0, long sBo = 0, long sBi = 0,
                      long sCo = 0, long sCi = 0, int zdiv = 1,
                      float alpha = 1.f, int relu = 0)
{
    constexpr int SM = 2 * (2 * 128 * 80 + 2 * TN * 80);
    static bool attr_set = false;
    if (!attr_set) {
        cudaFuncSetAttribute(mm_gemm<TN>, cudaFuncAttributeMaxDynamicSharedMemorySize, SM);
        attr_set = true;
    }
    dim3 g(N / TN, M / 128, Z);
    mm_gemm<TN><<<g, 256, SM>>>(Ah, Al, Bh, Bl, bias, C, Ch, Cl,
                                K, lda, ldb, ldc,
                                sAo, sAi, sBo, sBi, sCo, sCi, zdiv, alpha, relu);
}

static void cvt(const float* s, u16* h, u16* l, long n)
{
    long n4 = n >> 2;
    cvt_k<<<(unsigned)((n4 + 255) / 256), 256>>>((const float4*)s, (ushort4*)h, (ushort4*)l, (int)n4);
}

extern "C" void kernel_launch(void* const* d_in, const int* in_sizes, int n_in,
                              void* d_out, int out_size)
{
    const int*   SRC   = (const int*)  d_in[0];
    const float* EMB   = (const float*)d_in[1];
    const float* PE    = (const float*)d_in[2];
    const float* IN_W  = (const float*)d_in[3];
    const float* IN_B  = (const float*)d_in[4];
    const float* OUT_W = (const float*)d_in[5];
    const float* OUT_B = (const float*)d_in[6];
    const float* QP_W  = (const float*)d_in[7];
    const float* QP_B  = (const float*)d_in[8];
    const float* KP_W  = (const float*)d_in[9];
    const float* KP_B  = (const float*)d_in[10];
    const float* VP_W  = (const float*)d_in[11];
    const float* VP_B  = (const float*)d_in[12];
    const float* LAM   = (const float*)d_in[13];
    const float* FF1_W = (const float*)d_in[14];
    const float* FF1_B = (const float*)d_in[15];
    const float* FF2_W = (const float*)d_in[16];
    const float* FF2_B = (const float*)d_in[17];
    const float* LN1S  = (const float*)d_in[18];
    const float* LN1B  = (const float*)d_in[19];
    const float* LN2S  = (const float*)d_in[20];
    const float* LN2B  = (const float*)d_in[21];
    const float* FIN_W = (const float*)d_in[22];
    const float* FIN_B = (const float*)d_in[23];
    float* OUT = (float*)d_out;

    float *x, *qkv, *scores, *dense, *aproj, *qs, *ks, *vs, *sp, *ffh, *fft;
    cudaGetSymbolAddress((void**)&x, g_x);         cudaGetSymbolAddress((void**)&qkv, g_qkv);
    cudaGetSymbolAddress((void**)&scores, g_scores); cudaGetSymbolAddress((void**)&dense, g_dense);
    cudaGetSymbolAddress((void**)&aproj, g_aproj); cudaGetSymbolAddress((void**)&qs, g_Qs);
    cudaGetSymbolAddress((void**)&ks, g_Ks);       cudaGetSymbolAddress((void**)&vs, g_Vs);
    cudaGetSymbolAddress((void**)&sp, g_sparse);   cudaGetSymbolAddress((void**)&ffh, g_ffh);
    cudaGetSymbolAddress((void**)&fft, g_fft);

    u16 *xh, *xl, *qkvh, *qkvl, *Ph, *Pl, *dh, *dl, *fh, *fl, *vth, *vtl;
    cudaGetSymbolAddress((void**)&xh, g_xh);   cudaGetSymbolAddress((void**)&xl, g_xl);
    cudaGetSymbolAddress((void**)&qkvh, g_qkvh); cudaGetSymbolAddress((void**)&qkvl, g_qkvl);
    cudaGetSymbolAddress((void**)&Ph, g_Ph);   cudaGetSymbolAddress((void**)&Pl, g_Pl);
    cudaGetSymbolAddress((void**)&dh, g_dh);   cudaGetSymbolAddress((void**)&dl, g_dl);
    cudaGetSymbolAddress((void**)&fh, g_fh);   cudaGetSymbolAddress((void**)&fl, g_fl);
    cudaGetSymbolAddress((void**)&vth, g_vth); cudaGetSymbolAddress((void**)&vtl, g_vtl);

    u16 *inwh, *inwl, *outwh, *outwl, *qpwh, *qpwl, *kpwh, *kpwl, *vpwh, *vpwl;
    u16 *f1wh, *f1wl, *f2wh, *f2wl, *finwh, *finwl;
    cudaGetSymbolAddress((void**)&inwh, g_inwh);   cudaGetSymbolAddress((void**)&inwl, g_inwl);
    cudaGetSymbolAddress((void**)&outwh, g_outwh); cudaGetSymbolAddress((void**)&outwl, g_outwl);
    cudaGetSymbolAddress((void**)&qpwh, g_qpwh);   cudaGetSymbolAddress((void**)&qpwl, g_qpwl);
    cudaGetSymbolAddress((void**)&kpwh, g_kpwh);   cudaGetSymbolAddress((void**)&kpwl, g_kpwl);
    cudaGetSymbolAddress((void**)&vpwh, g_vpwh);   cudaGetSymbolAddress((void**)&vpwl, g_vpwl);
    cudaGetSymbolAddress((void**)&f1wh, g_f1wh);   cudaGetSymbolAddress((void**)&f1wl, g_f1wl);
    cudaGetSymbolAddress((void**)&f2wh, g_f2wh);   cudaGetSymbolAddress((void**)&f2wl, g_f2wl);
    cudaGetSymbolAddress((void**)&finwh, g_finwh); cudaGetSymbolAddress((void**)&finwl, g_finwl);

    // convert all weights once
    cvt(IN_W,  inwh,  inwl,  (long)LAYERS * 3 * DIM * DIM);
    cvt(OUT_W, outwh, outwl, (long)LAYERS * DIM * DIM);
    cvt(QP_W,  qpwh,  qpwl,  (long)LAYERS * RANK * DIM);
    cvt(KP_W,  kpwh,  kpwl,  (long)LAYERS * RANK * DIM);
    cvt(VP_W,  vpwh,  vpwl,  (long)LAYERS * DIM * DIM);
    cvt(FF1_W, f1wh,  f1wl,  (long)LAYERS * FFD * DIM);
    cvt(FF2_W, f2wh,  f2wl,  (long)LAYERS * DIM * FFD);
    cvt(FIN_W, finwh, finwl, (long)VOCAB * DIM);

    embed_k<<<TOKENS, 256>>>(SRC, EMB, PE, x, xh, xl);

    for (int l = 0; l < LAYERS; l++) {
        long wq  = (long)l * 3 * DIM * DIM;
        long wo  = (long)l * DIM * DIM;
        long wp  = (long)l * RANK * DIM;
        long wf1 = (long)l * FFD * DIM;
        long wf2 = (long)l * DIM * FFD;

        // qkv = x @ in_w^T + in_b  (fp32 + bf16 planes)
        launch_tc<128>(xh, xl, inwh + wq, inwl + wq, IN_B + (long)l * 3 * DIM,
                       qkv, qkvh, qkvl, TOKENS, 3 * DIM, DIM, DIM, DIM, 3 * DIM);

        // scores = Q @ K^T / 8 per (b,h)
        launch_tc<128>(qkvh, qkvl, qkvh + DIM, qkvl + DIM, nullptr,
                       scores, nullptr, nullptr,
                       SEQ, SEQ, HDIM, 3 * DIM, 3 * DIM, SEQ,
                       16, (long)SEQ * 3 * DIM, (long)HDIM,
                       (long)SEQ * 3 * DIM, (long)HDIM,
                       (long)HEADS * SEQ * SEQ, (long)SEQ * SEQ,
                       HEADS, 0.125f, 0);

        // softmax -> P hi/lo planes
        softmax_rows<<<16 * SEQ, 256>>>(scores, Ph, Pl);

        // V^T planes
        vt_k<<<dim3(SEQ / 256, HDIM, 16), 256>>>(qkv, vth, vtl);

        // dense = P @ V per (b,h)  -> fp32 + planes
        launch_tc<64>(Ph, Pl, vth, vtl, nullptr, dense, dh, dl,
                      SEQ, HDIM, SEQ, SEQ, SEQ, DIM,
                      16, (long)HEADS * SEQ * SEQ, (long)SEQ * SEQ,
                      (long)HEADS * HDIM * SEQ, (long)HDIM * SEQ,
                      (long)SEQ * DIM, (long)HDIM,
                      HEADS, 1.f, 0);

        // dense projection
        launch_tc<128>(dh, dl, outwh + wo, outwl + wo, OUT_B + (long)l * DIM,
                       aproj, nullptr, nullptr, TOKENS, DIM, DIM, DIM, DIM, DIM);

        // low-rank projections (fp32 outputs for sparse path)
        launch_tc<64>(xh, xl, qpwh + wp, qpwl + wp, QP_B + (long)l * RANK,
                      qs, nullptr, nullptr, TOKENS, RANK, DIM, DIM, DIM, RANK);
        launch_tc<64>(xh, xl, kpwh + wp, kpwl + wp, KP_B + (long)l * RANK,
                      ks, nullptr, nullptr, TOKENS, RANK, DIM, DIM, DIM, RANK);
        launch_tc<128>(xh, xl, vpwh + wo, vpwl + wo, VP_B + (long)l * DIM,
                       vs, nullptr, nullptr, TOKENS, DIM, DIM, DIM, DIM, DIM);

        sparse_attn<<<TOKENS, 256>>>(qs, ks, vs, sp);

        fuse_ln1_k<<<TOKENS, 256>>>(x, aproj, sp, LAM, l,
                                    LN1S + (long)l * DIM, LN1B + (long)l * DIM, xh, xl);

        // FFN
        launch_tc<128>(xh, xl, f1wh + wf1, f1wl + wf1, FF1_B + (long)l * FFD,
                       ffh, fh, fl, TOKENS, FFD, DIM, DIM, DIM, FFD,
                       1, 0, 0, 0, 0, 0, 0, 1, 1.f, 1);
        launch_tc<128>(fh, fl, f2wh + wf2, f2wl + wf2, FF2_B + (long)l * DIM,
                       fft, nullptr, nullptr, TOKENS, DIM, FFD, FFD, FFD, DIM);

        add_ln2_k<<<TOKENS, 256>>>(x, fft, LN2S + (long)l * DIM, LN2B + (long)l * DIM, xh, xl);
    }

    // final vocab projection
    launch_tc<128>(xh, xl, finwh, finwl, FIN_B, OUT, nullptr, nullptr,
                   TOKENS, VOCAB, DIM, DIM, DIM, VOCAB);
}